// round 5
// baseline (speedup 1.0000x reference)
#include <cuda_runtime.h>

// Fused beam reorder + suffix append for KV cache.
// Shapes: L=8, G=128, NH=8, T=128, HD=64, fp32.
//   out_k[l,g,h,t,:] = (t==pos) ? k_new[l,g,h,0,:] : k_buf[l,beam[g],h,t,:]
//   out_v analogous. Output = [k ; v] concatenated.
//
// float4 (16B) units: NEL4 = 2^24 per buffer; beam stride = 2^14.
//   t=(j>>4)&127; g=(j>>14)&127; gather src = j + (beam[g]-g)<<14
//   append src = ((j>>11)<<4)|(j&15)   ({k,v}_new is [L,G,NH,1,HD])
//
// Traffic: compulsory ≈ 836 MB (512 MB writes + unique-beam reads; L2 dedups
// duplicate beams). To make the dedup hit rate ~100%, blocks are assigned to
// beams through a beam-sorted permutation (d_order), so all readers of the
// same source beam run adjacently and their reads coincide in L2.
//
// Block = 256 thr x ILP 4 = 1024 contiguous float4 (one 1024-aligned chunk).
// Per (l,g): 16 chunks. Per l: 128 g-slots x 16. g/is_v/delta uniform per blk.

static constexpr unsigned NEL4  = 1u << 24;   // float4s per buffer
static constexpr unsigned TOTAL = 1u << 25;   // k + v
static constexpr int      ILP   = 4;
static constexpr int      THREADS = 256;
static constexpr unsigned BLOCKS_PER_BUF = NEL4 / (THREADS * ILP); // 16384

__device__ int d_order[128];   // g's sorted (stable) by beam[g]

__global__ void compute_order_kernel(const int* __restrict__ beam)
{
    __shared__ int b[128];
    const int g = threadIdx.x;           // 128 threads
    b[g] = beam[g];
    __syncthreads();
    const int mine = b[g];
    int rank = 0;
    #pragma unroll 8
    for (int i = 0; i < 128; i++) {
        const int v = b[i];
        rank += (v < mine) || (v == mine && i < g);
    }
    d_order[rank] = g;                   // deterministic stable rank sort
}

__global__ void __launch_bounds__(THREADS, 8)
beam_reorder_append_kernel(const float4* __restrict__ kb,
                           const float4* __restrict__ vb,
                           const float4* __restrict__ kn,
                           const float4* __restrict__ vn,
                           const int*    __restrict__ beam,
                           const int*    __restrict__ posp,
                           float4*       __restrict__ out)
{
    const unsigned blk  = blockIdx.x;
    const bool is_v     = blk >= BLOCKS_PER_BUF;          // uniform
    const unsigned b2   = blk & (BLOCKS_PER_BUF - 1);
    const unsigned l    = b2 >> 11;                       // 2048 blocks per l
    const unsigned slot = (b2 >> 4) & 127;                // beam-sorted slot
    const unsigned inner= b2 & 15;                        // chunk within (l,g)

    const unsigned g    = (unsigned)d_order[slot];        // uniform per block
    const unsigned jbase= (l << 21) | (g << 14) | (inner << 10);

    const int pos = *posp;                                // uniform
    const unsigned delta = ((unsigned)(beam[g] - (int)g)) << 14;  // uniform

    const float4* __restrict__ buf  = is_v ? vb : kb;
    const float4* __restrict__ nbuf = is_v ? vn : kn;
    const unsigned obase = jbase + (is_v ? NEL4 : 0u);

    float4 r[ILP];

    // Front-batch all 4 independent 128-bit loads (MLP_p1 = 4), L2-only.
    #pragma unroll
    for (int k = 0; k < ILP; k++) {
        const unsigned j = jbase + threadIdx.x + (unsigned)k * THREADS;
        const unsigned t = (j >> 4) & 127;
        const bool app = (t == (unsigned)pos);
        const unsigned sidx = app ? (((j >> 11) << 4) | (j & 15))
                                  : (j + delta);
        const float4* __restrict__ src = app ? nbuf : buf;
        r[k] = __ldcg(src + sidx);
    }

    // Streaming stores: output never re-read.
    #pragma unroll
    for (int k = 0; k < ILP; k++)
        __stcs(out + obase + threadIdx.x + (unsigned)k * THREADS, r[k]);
}

extern "C" void kernel_launch(void* const* d_in, const int* in_sizes, int n_in,
                              void* d_out, int out_size)
{
    const float4* kb   = (const float4*)d_in[0];  // k_buf  [L,G,NH,T,HD] fp32
    const float4* vb   = (const float4*)d_in[1];  // v_buf
    const float4* kn   = (const float4*)d_in[2];  // k_new  [L,G,NH,1,HD]
    const float4* vn   = (const float4*)d_in[3];  // v_new
    const int*    beam = (const int*)d_in[4];     // new_beam_idx [G]
    const int*    posp = (const int*)d_in[5];     // pos (scalar, device-side)
    float4*       out  = (float4*)d_out;          // [2,L,G,NH,T,HD] fp32

    compute_order_kernel<<<1, 128>>>(beam);
    beam_reorder_append_kernel<<<2 * BLOCKS_PER_BUF, THREADS>>>(
        kb, vb, kn, vn, beam, posp, out);
}